// round 1
// baseline (speedup 1.0000x reference)
#include <cuda_runtime.h>

// Sequence_53300544143404: 2-layer LSTM (H=51), B=4096, T=1000 + 100 future steps.
// Strategy: persistent per-CTA batch-slab, weights in smem, f32x2 packed FMA GEMMs,
// cell state resident in registers for all 1100 steps.

#define Hh    51
#define HP    52           // padded hidden
#define BATCH 4096
#define T_IN  1000
#define FUT   100
#define T_TOT (T_IN + FUT)
#define RPC   28           // batch rows per CTA
#define RG    7            // row groups of 4 rows
#define NACT  (HP * RG)    // 364 active compute threads
#define NTHR  384
#define NCTA  ((BATCH + RPC - 1) / RPC)   // 147

typedef unsigned long long ull;

struct SmemLayout {
    // Weights layer1: [h][k][gate i,f,g,o]; k in 0..50 = W_hh1 cols, k==51 = W_ih1 (x col), k==52 pad
    float WA[HP][53][4];
    // Weights layer2: k 0..50 = W_ih2 (input h1), k==51 zero (x slot), k 52..102 = W_hh2 (h2), 103/104 pad
    float WB[HP][105][4];
    // Input buffers, duplicated pairs: B[k][2r] = B[k][2r+1] = value for row r. Row stride 64 floats.
    float B1[HP][64];      // [h1 rows 0..50][x at row 51], duplicated over 28 rows
    float B2[HP][64];      // h2 rows 0..50, row 51 stays zero
    float BA[HP][4];       // b_ih1 + b_hh1 per (h, gate)
    float BB[HP][4];       // b_ih2 + b_hh2
    float WL[HP];          // W_lin
    float blin;
};

__device__ __forceinline__ ull ffma2(ull a, ull b, ull c) {
    ull d;
    asm("fma.rn.f32x2 %0, %1, %2, %3;" : "=l"(d) : "l"(a), "l"(b), "l"(c));
    return d;
}
__device__ __forceinline__ ull pack2(float lo, float hi) {
    ull r; asm("mov.b64 %0, {%1, %2};" : "=l"(r) : "f"(lo), "f"(hi)); return r;
}
__device__ __forceinline__ void unpack2(ull v, float& lo, float& hi) {
    asm("mov.b64 {%0, %1}, %2;" : "=f"(lo), "=f"(hi) : "l"(v));
}
__device__ __forceinline__ float sig_(float x) {
    return __fdividef(1.0f, 1.0f + __expf(-x));
}
__device__ __forceinline__ float tanh_(float x) {
    float a = fabsf(x);
    float e = __expf(-2.0f * a);
    float r = __fdividef(1.0f - e, 1.0f + e);
    return copysignf(r, x);
}
// gates (i,f) packed in aIF, (g,o) in aGO; updates c, returns new h
__device__ __forceinline__ float cell_update(ull aIF, ull aGO, float& c) {
    float gi, gf, gg, go;
    unpack2(aIF, gi, gf);
    unpack2(aGO, gg, go);
    float cn = sig_(gf) * c + sig_(gi) * tanh_(gg);
    c = cn;
    return sig_(go) * tanh_(cn);
}

// One K=52 GEMM sub-block. w advances by 52*4 floats, v walks rows of a B buffer.
__device__ __forceinline__ void gemm_block(const float*& w, const float* v,
                                           ull& aIF0, ull& aGO0, ull& aIF1, ull& aGO1,
                                           ull& aIF2, ull& aGO2, ull& aIF3, ull& aGO3) {
    #pragma unroll 4
    for (int k = 0; k < HP; ++k) {
        ulonglong2 wv  = *reinterpret_cast<const ulonglong2*>(w);       // (Wi,Wf),(Wg,Wo)
        ulonglong2 v01 = *reinterpret_cast<const ulonglong2*>(v);       // (x0,x0),(x1,x1)
        ulonglong2 v23 = *reinterpret_cast<const ulonglong2*>(v + 4);   // (x2,x2),(x3,x3)
        w += 4; v += 64;
        aIF0 = ffma2(wv.x, v01.x, aIF0);  aGO0 = ffma2(wv.y, v01.x, aGO0);
        aIF1 = ffma2(wv.x, v01.y, aIF1);  aGO1 = ffma2(wv.y, v01.y, aGO1);
        aIF2 = ffma2(wv.x, v23.x, aIF2);  aGO2 = ffma2(wv.y, v23.x, aGO2);
        aIF3 = ffma2(wv.x, v23.y, aIF3);  aGO3 = ffma2(wv.y, v23.y, aGO3);
    }
}

extern __shared__ __align__(16) char smem_raw[];

__global__ __launch_bounds__(NTHR, 1)
void lstm_seq_kernel(const float* __restrict__ xin,
                     const float* __restrict__ W_ih1, const float* __restrict__ W_hh1,
                     const float* __restrict__ b_ih1, const float* __restrict__ b_hh1,
                     const float* __restrict__ W_ih2, const float* __restrict__ W_hh2,
                     const float* __restrict__ b_ih2, const float* __restrict__ b_hh2,
                     const float* __restrict__ W_lin, const float* __restrict__ b_lin,
                     float* __restrict__ out)
{
    SmemLayout* s = reinterpret_cast<SmemLayout*>(smem_raw);
    const int tid = threadIdx.x;

    // ---------------- one-time smem staging ----------------
    for (int i = tid; i < HP * 53 * 4; i += NTHR) {
        int h = i / (53 * 4); int rem = i - h * 53 * 4; int k = rem >> 2; int g = rem & 3;
        float v = 0.f;
        if (h < Hh) {
            if (k < Hh)       v = W_hh1[(g * Hh + h) * Hh + k];
            else if (k == Hh) v = W_ih1[g * Hh + h];
        }
        s->WA[h][k][g] = v;
    }
    for (int i = tid; i < HP * 105 * 4; i += NTHR) {
        int h = i / (105 * 4); int rem = i - h * 105 * 4; int k = rem >> 2; int g = rem & 3;
        float v = 0.f;
        if (h < Hh) {
            if (k < Hh)                         v = W_ih2[(g * Hh + h) * Hh + k];
            else if (k >= HP && k < HP + Hh)    v = W_hh2[(g * Hh + h) * Hh + (k - HP)];
        }
        s->WB[h][k][g] = v;
    }
    for (int i = tid; i < HP * 4; i += NTHR) {
        int h = i >> 2, g = i & 3;
        float a = 0.f, b = 0.f;
        if (h < Hh) {
            a = b_ih1[g * Hh + h] + b_hh1[g * Hh + h];
            b = b_ih2[g * Hh + h] + b_hh2[g * Hh + h];
        }
        s->BA[h][g] = a; s->BB[h][g] = b;
    }
    for (int i = tid; i < HP * 64; i += NTHR) { s->B1[0][i] = 0.f; s->B2[0][i] = 0.f; }
    if (tid < HP) s->WL[tid] = (tid < Hh) ? W_lin[tid] : 0.f;
    if (tid == 0) s->blin = b_lin[0];
    __syncthreads();

    // ---------------- per-thread roles ----------------
    const bool active = tid < NACT;
    const int h   = tid / RG;          // 0..51 (51 = pad row, zero weights)
    const int rg  = tid - h * RG;      // 0..6
    const int voff = rg * 8;           // float offset into duplicated row buffers
    const int row = blockIdx.x * RPC + tid;   // only meaningful for tid < RPC

    float c1_0 = 0.f, c1_1 = 0.f, c1_2 = 0.f, c1_3 = 0.f;
    float c2_0 = 0.f, c2_1 = 0.f, c2_2 = 0.f, c2_3 = 0.f;
    float xv = 0.f, out_prev = 0.f;
    if (tid < RPC && row < BATCH) xv = xin[row * T_IN];   // prefetch x[t=0]

    const float* waBase = &s->WA[h][0][0];
    const float* wbBase = &s->WB[h][0][0];

    // ---------------- time loop ----------------
    for (int t = 0; t < T_TOT; ++t) {
        // stage x_t into the x slot (row 51 of B1), duplicated; prefetch x_{t+1}
        if (tid < RPC) {
            float xs = (t < T_IN) ? xv : out_prev;
            *reinterpret_cast<ull*>(&s->B1[Hh][2 * tid]) = pack2(xs, xs);
            if (t + 1 < T_IN && row < BATCH) xv = xin[row * T_IN + t + 1];
        }
        __syncthreads();   // S1: x staged, previous-step buffers quiescent

        ull aIF0, aGO0, aIF1, aGO1, aIF2, aGO2, aIF3, aGO3;
        if (active) {
            // GEMM-A: gates1 = [W_hh1 | W_ih1] @ [h1; x] + bias1
            ull bif = pack2(s->BA[h][0], s->BA[h][1]);
            ull bgo = pack2(s->BA[h][2], s->BA[h][3]);
            aIF0 = aIF1 = aIF2 = aIF3 = bif;
            aGO0 = aGO1 = aGO2 = aGO3 = bgo;
            const float* w = waBase;
            gemm_block(w, &s->B1[0][voff], aIF0, aGO0, aIF1, aGO1, aIF2, aGO2, aIF3, aGO3);
        }
        __syncthreads();   // S2: all GEMM-A reads of B1 done before h1 overwrite

        if (active && h < Hh) {
            float h0 = cell_update(aIF0, aGO0, c1_0);
            float h1v = cell_update(aIF1, aGO1, c1_1);
            float h2v = cell_update(aIF2, aGO2, c1_2);
            float h3v = cell_update(aIF3, aGO3, c1_3);
            *reinterpret_cast<float4*>(&s->B1[h][voff])     = make_float4(h0, h0, h1v, h1v);
            *reinterpret_cast<float4*>(&s->B1[h][voff + 4]) = make_float4(h2v, h2v, h3v, h3v);
        }
        __syncthreads();   // S3: h1_new visible

        if (active) {
            // GEMM-B: gates2 = [W_ih2 | W_hh2] @ [h1_new; h2] + bias2 (x slot hits zero col)
            ull bif = pack2(s->BB[h][0], s->BB[h][1]);
            ull bgo = pack2(s->BB[h][2], s->BB[h][3]);
            aIF0 = aIF1 = aIF2 = aIF3 = bif;
            aGO0 = aGO1 = aGO2 = aGO3 = bgo;
            const float* w = wbBase;
            gemm_block(w, &s->B1[0][voff], aIF0, aGO0, aIF1, aGO1, aIF2, aGO2, aIF3, aGO3);
            gemm_block(w, &s->B2[0][voff], aIF0, aGO0, aIF1, aGO1, aIF2, aGO2, aIF3, aGO3);
        }
        __syncthreads();   // S4: all GEMM-B reads of B2 done before h2 overwrite

        if (active && h < Hh) {
            float h0 = cell_update(aIF0, aGO0, c2_0);
            float h1v = cell_update(aIF1, aGO1, c2_1);
            float h2v = cell_update(aIF2, aGO2, c2_2);
            float h3v = cell_update(aIF3, aGO3, c2_3);
            *reinterpret_cast<float4*>(&s->B2[h][voff])     = make_float4(h0, h0, h1v, h1v);
            *reinterpret_cast<float4*>(&s->B2[h][voff + 4]) = make_float4(h2v, h2v, h3v, h3v);
        }
        __syncthreads();   // S5: h2_new visible

        // linear head: out = W_lin . h2 + b_lin (one thread per row)
        if (tid < RPC) {
            const float* col = &s->B2[0][2 * tid];
            float a0 = s->blin, a1 = 0.f, a2 = 0.f;
            #pragma unroll
            for (int k3 = 0; k3 < Hh; k3 += 3) {
                a0 += s->WL[k3]     * col[(k3)     * 64];
                a1 += s->WL[k3 + 1] * col[(k3 + 1) * 64];
                a2 += s->WL[k3 + 2] * col[(k3 + 2) * 64];
            }
            float o = a0 + a1 + a2;
            out_prev = o;
            if (row < BATCH) out[row * T_TOT + t] = o;
        }
    }
}

extern "C" void kernel_launch(void* const* d_in, const int* in_sizes, int n_in,
                              void* d_out, int out_size) {
    (void)in_sizes; (void)n_in; (void)out_size;
    const size_t smem = sizeof(SmemLayout);
    cudaFuncSetAttribute(lstm_seq_kernel, cudaFuncAttributeMaxDynamicSharedMemorySize, (int)smem);
    lstm_seq_kernel<<<NCTA, NTHR, smem>>>(
        (const float*)d_in[0],   // inputs [B, T]
        (const float*)d_in[1],   // W_ih1 [204,1]
        (const float*)d_in[2],   // W_hh1 [204,51]
        (const float*)d_in[3],   // b_ih1 [204]
        (const float*)d_in[4],   // b_hh1 [204]
        (const float*)d_in[5],   // W_ih2 [204,51]
        (const float*)d_in[6],   // W_hh2 [204,51]
        (const float*)d_in[7],   // b_ih2 [204]
        (const float*)d_in[8],   // b_hh2 [204]
        (const float*)d_in[9],   // W_lin [1,51]
        (const float*)d_in[10],  // b_lin [1]
        (float*)d_out);          // out [B, 1100]
}

// round 2
// speedup vs baseline: 1.2879x; 1.2879x over previous
#include <cuda_runtime.h>

// Sequence_53300544143404: 2-layer LSTM (H=51), B=4096, T=1000 + 100 future steps.
// R2: 768 threads (24 warps/SM), 2 rows/thread, ping-pong state buffers (3 barriers/step),
// warp-parallel linear head with shuffle reduction. Weights in smem, f32x2 packed FMAs,
// cell state register-resident for all 1100 steps.

#define Hh    51
#define HP    52
#define BATCH 4096
#define T_IN  1000
#define FUT   100
#define T_TOT (T_IN + FUT)
#define RPC   28            // batch rows per CTA
#define RGN   14            // row groups of 2 rows
#define NACT  (HP * RGN)    // 728 active compute threads
#define NTHR  768
#define NCTA  ((BATCH + RPC - 1) / RPC)   // 147
#define BROW  68            // padded floats per state-buffer row (16B-aligned, bank-spread)

typedef unsigned long long ull;

struct SmemLayout {
    // Layer1 weights: [h][k][gate i,f,g,o]; k 0..50 = W_hh1 cols, k==51 = W_ih1 (x), k==52 pad
    float WA[HP][53][4];
    // Layer2 weights: k 0..50 = W_ih2 (h1 input), k==51 zero (x slot), k 52..102 = W_hh2, 103/104 pad
    float WB[HP][105][4];
    // Ping-pong state buffers, duplicated pairs: B[p][k][2r]=B[p][k][2r+1]=value of row r.
    float B1[2][HP][BROW];  // h1 rows 0..50, row 51 = x slot
    float B2[2][HP][BROW];  // h2 rows 0..50, row 51 stays zero
    float BA[HP][4];        // b_ih1 + b_hh1
    float BB[HP][4];        // b_ih2 + b_hh2
    float WL[HP];
    float blin;
};

__device__ __forceinline__ ull ffma2(ull a, ull b, ull c) {
    ull d;
    asm("fma.rn.f32x2 %0, %1, %2, %3;" : "=l"(d) : "l"(a), "l"(b), "l"(c));
    return d;
}
__device__ __forceinline__ ull pack2(float lo, float hi) {
    ull r; asm("mov.b64 %0, {%1, %2};" : "=l"(r) : "f"(lo), "f"(hi)); return r;
}
__device__ __forceinline__ void unpack2(ull v, float& lo, float& hi) {
    asm("mov.b64 {%0, %1}, %2;" : "=f"(lo), "=f"(hi) : "l"(v));
}
__device__ __forceinline__ float sig_(float x) {
    return __fdividef(1.0f, 1.0f + __expf(-x));
}
__device__ __forceinline__ float tanh_(float x) {
    float a = fabsf(x);
    float e = __expf(-2.0f * a);
    float r = __fdividef(1.0f - e, 1.0f + e);
    return copysignf(r, x);
}
__device__ __forceinline__ float cell_update(ull aIF, ull aGO, float& c) {
    float gi, gf, gg, go;
    unpack2(aIF, gi, gf);
    unpack2(aGO, gg, go);
    float cn = sig_(gf) * c + sig_(gi) * tanh_(gg);
    c = cn;
    return sig_(go) * tanh_(cn);
}

// One K=52 GEMM sub-block: per k, 16B weight load + 16B duplicated-value load, 4 FFMA2.
__device__ __forceinline__ void gemm_block(const float*& w, const float* v,
                                           ull& aIF0, ull& aGO0, ull& aIF1, ull& aGO1) {
    #pragma unroll 4
    for (int k = 0; k < HP; ++k) {
        ulonglong2 wv = *reinterpret_cast<const ulonglong2*>(w);   // (Wi,Wf),(Wg,Wo)
        ulonglong2 vv = *reinterpret_cast<const ulonglong2*>(v);   // (x0,x0),(x1,x1)
        w += 4; v += BROW;
        aIF0 = ffma2(wv.x, vv.x, aIF0);  aGO0 = ffma2(wv.y, vv.x, aGO0);
        aIF1 = ffma2(wv.x, vv.y, aIF1);  aGO1 = ffma2(wv.y, vv.y, aGO1);
    }
}

extern __shared__ __align__(16) char smem_raw[];

__global__ __launch_bounds__(NTHR, 1)
void lstm_seq_kernel(const float* __restrict__ xin,
                     const float* __restrict__ W_ih1, const float* __restrict__ W_hh1,
                     const float* __restrict__ b_ih1, const float* __restrict__ b_hh1,
                     const float* __restrict__ W_ih2, const float* __restrict__ W_hh2,
                     const float* __restrict__ b_ih2, const float* __restrict__ b_hh2,
                     const float* __restrict__ W_lin, const float* __restrict__ b_lin,
                     float* __restrict__ out)
{
    SmemLayout* s = reinterpret_cast<SmemLayout*>(smem_raw);
    const int tid = threadIdx.x;

    // ---------------- one-time smem staging ----------------
    for (int i = tid; i < HP * 53 * 4; i += NTHR) {
        int h = i / (53 * 4); int rem = i - h * 53 * 4; int k = rem >> 2; int g = rem & 3;
        float v = 0.f;
        if (h < Hh) {
            if (k < Hh)       v = W_hh1[(g * Hh + h) * Hh + k];
            else if (k == Hh) v = W_ih1[g * Hh + h];
        }
        s->WA[h][k][g] = v;
    }
    for (int i = tid; i < HP * 105 * 4; i += NTHR) {
        int h = i / (105 * 4); int rem = i - h * 105 * 4; int k = rem >> 2; int g = rem & 3;
        float v = 0.f;
        if (h < Hh) {
            if (k < Hh)                      v = W_ih2[(g * Hh + h) * Hh + k];
            else if (k >= HP && k < HP + Hh) v = W_hh2[(g * Hh + h) * Hh + (k - HP)];
        }
        s->WB[h][k][g] = v;
    }
    for (int i = tid; i < HP * 4; i += NTHR) {
        int h = i >> 2, g = i & 3;
        float a = 0.f, b = 0.f;
        if (h < Hh) {
            a = b_ih1[g * Hh + h] + b_hh1[g * Hh + h];
            b = b_ih2[g * Hh + h] + b_hh2[g * Hh + h];
        }
        s->BA[h][g] = a; s->BB[h][g] = b;
    }
    for (int i = tid; i < 2 * HP * BROW; i += NTHR) {
        s->B1[0][0][i] = 0.f;
        s->B2[0][0][i] = 0.f;
    }
    if (tid < HP) s->WL[tid] = (tid < Hh) ? W_lin[tid] : 0.f;
    if (tid == 0) s->blin = b_lin[0];
    __syncthreads();

    // ---------------- per-thread roles ----------------
    const bool active = tid < NACT;
    const int h    = tid / RGN;        // 0..51 (51 = zero-weight pad row)
    const int rg   = tid - h * RGN;    // 0..13
    const int voff = rg * 4;           // float offset into duplicated row buffers (2 rows)

    // head/stager role: 224 threads = 28 rows x 8 lanes; lane j==0 also stages x
    const bool is_head   = tid < RPC * 8;
    const int  hrow      = tid >> 3;               // 0..27
    const int  hj        = tid & 7;                // 0..7
    const bool is_stager = is_head && (hj == 0);
    const int  grow      = blockIdx.x * RPC + hrow;

    float c1_0 = 0.f, c1_1 = 0.f, c2_0 = 0.f, c2_1 = 0.f;
    float xv = 0.f, out_prev = 0.f;
    if (is_stager && grow < BATCH) xv = xin[grow * T_IN];   // prefetch x[t=0]

    const float* waBase = &s->WA[h][0][0];
    const float* wbBase = &s->WB[h][0][0];

    // ---------------- time loop ----------------
    for (int t = 0; t < T_TOT; ++t) {
        const int p = t & 1;
        float* cur1 = &s->B1[p][0][0];
        float* nxt1 = &s->B1[p ^ 1][0][0];
        float* cur2 = &s->B2[p][0][0];
        float* nxt2 = &s->B2[p ^ 1][0][0];

        // stage x_t into x slot (row 51 of cur1), duplicated; prefetch x_{t+1}
        if (is_stager) {
            float xs = (t < T_IN) ? xv : out_prev;
            *reinterpret_cast<ull*>(cur1 + Hh * BROW + 2 * hrow) = pack2(xs, xs);
            if (t + 1 < T_IN && grow < BATCH) xv = xin[grow * T_IN + t + 1];
        }
        __syncthreads();   // S1: x staged; step t-1 fully complete

        ull aIF0, aGO0, aIF1, aGO1;
        if (active) {
            // gates1 = [W_hh1 | W_ih1] @ [h1; x] + bias1
            aIF0 = aIF1 = pack2(s->BA[h][0], s->BA[h][1]);
            aGO0 = aGO1 = pack2(s->BA[h][2], s->BA[h][3]);
            const float* w = waBase;
            gemm_block(w, cur1 + voff, aIF0, aGO0, aIF1, aGO1);
        }

        if (active && h < Hh) {
            float h0 = cell_update(aIF0, aGO0, c1_0);
            float h1v = cell_update(aIF1, aGO1, c1_1);
            *reinterpret_cast<float4*>(nxt1 + h * BROW + voff) = make_float4(h0, h0, h1v, h1v);
        }
        __syncthreads();   // S3: h1_new visible

        if (active) {
            // gates2 = [W_ih2 | W_hh2] @ [h1_new; h2] + bias2 (x slot hits zero weights)
            aIF0 = aIF1 = pack2(s->BB[h][0], s->BB[h][1]);
            aGO0 = aGO1 = pack2(s->BB[h][2], s->BB[h][3]);
            const float* w = wbBase;
            gemm_block(w, nxt1 + voff, aIF0, aGO0, aIF1, aGO1);
            gemm_block(w, cur2 + voff, aIF0, aGO0, aIF1, aGO1);
        }

        if (active && h < Hh) {
            float h0 = cell_update(aIF0, aGO0, c2_0);
            float h1v = cell_update(aIF1, aGO1, c2_1);
            *reinterpret_cast<float4*>(nxt2 + h * BROW + voff) = make_float4(h0, h0, h1v, h1v);
        }
        __syncthreads();   // S5: h2_new visible

        // linear head: out = W_lin . h2 + b_lin; 8 lanes per row + shuffle reduce
        if (is_head) {
            float a = 0.f;
            const float* col = nxt2 + 2 * hrow;
            for (int k = hj; k < Hh; k += 8)
                a += s->WL[k] * col[k * BROW];
            a += __shfl_xor_sync(0xFFFFFFFFu, a, 1);
            a += __shfl_xor_sync(0xFFFFFFFFu, a, 2);
            a += __shfl_xor_sync(0xFFFFFFFFu, a, 4);
            if (hj == 0) {
                float o = a + s->blin;
                out_prev = o;
                if (grow < BATCH) out[grow * T_TOT + t] = o;
            }
        }
    }
}

extern "C" void kernel_launch(void* const* d_in, const int* in_sizes, int n_in,
                              void* d_out, int out_size) {
    (void)in_sizes; (void)n_in; (void)out_size;
    const size_t smem = sizeof(SmemLayout);
    cudaFuncSetAttribute(lstm_seq_kernel, cudaFuncAttributeMaxDynamicSharedMemorySize, (int)smem);
    lstm_seq_kernel<<<NCTA, NTHR, smem>>>(
        (const float*)d_in[0],   // inputs [B, T]
        (const float*)d_in[1],   // W_ih1 [204,1]
        (const float*)d_in[2],   // W_hh1 [204,51]
        (const float*)d_in[3],   // b_ih1 [204]
        (const float*)d_in[4],   // b_hh1 [204]
        (const float*)d_in[5],   // W_ih2 [204,51]
        (const float*)d_in[6],   // W_hh2 [204,51]
        (const float*)d_in[7],   // b_ih2 [204]
        (const float*)d_in[8],   // b_hh2 [204]
        (const float*)d_in[9],   // W_lin [1,51]
        (const float*)d_in[10],  // b_lin [1]
        (float*)d_out);          // out [B, 1100]
}

// round 3
// speedup vs baseline: 1.7433x; 1.3536x over previous
#include <cuda_runtime.h>

// Sequence_53300544143404: 2-layer LSTM (H=51), B=4096, T=1000 + 100 future.
// R3: smem-bandwidth-targeted retile. Thread = (2 h-rows x 4 batch rows):
// 48B smem per k-iter for 32 FMAs (1.5 B/FMA, was 4). Unduplicated value
// buffers + register pair-packing. 224 threads, 3 barriers/step, exp activations.

#define Hh    51
#define BATCH 4096
#define T_IN  1000
#define FUT   100
#define T_TOT (T_IN + FUT)
#define HPAIR 26            // h-pairs (covers h 0..51, h=51 zero-padded)
#define RPC   28            // batch rows per CTA
#define RG4   7             // groups of 4 rows
#define NACT  (HPAIR * RG4) // 182 compute threads
#define NTHR  224           // 7 warps (head needs 28x8)
#define NCTA  ((BATCH + RPC - 1) / RPC)   // 147
#define BROW  28            // floats per state row (batch dim), 16B-aligned

typedef unsigned long long ull;

struct SmemLayout {
    // Layer1 weights: [hp][k][8] = gates (i,f,g,o) for h=2hp then h=2hp+1.
    // k 0..50 = W_hh1 columns, k==51 = W_ih1 (x column).
    float WA[HPAIR][52][8];
    // Layer2: k 0..50 = W_ih2 (h1 input), k==51 = zero (x slot of B1),
    //         k 52..102 = W_hh2 (h2 input), k==103 = zero pad.
    float WB[HPAIR][104][8];
    // Ping-pong state buffers, unduplicated: B[p][k][row].
    float B1[2][52][BROW];  // rows k=0..50 h1, k=51 = x slot
    float B2[2][52][BROW];  // rows k=0..50 h2, k=51 stays zero
    float BA[HPAIR][8];     // b_ih1+b_hh1, per (hp, 2h x 4 gates)
    float BB[HPAIR][8];
    float WL[52];
    float blin;
};

__device__ __forceinline__ ull ffma2(ull a, ull b, ull c) {
    ull d;
    asm("fma.rn.f32x2 %0, %1, %2, %3;" : "=l"(d) : "l"(a), "l"(b), "l"(c));
    return d;
}
__device__ __forceinline__ ull pack2(float lo, float hi) {
    ull r; asm("mov.b64 %0, {%1, %2};" : "=l"(r) : "f"(lo), "f"(hi)); return r;
}
__device__ __forceinline__ void unpack2(ull v, float& lo, float& hi) {
    asm("mov.b64 {%0, %1}, %2;" : "=f"(lo), "=f"(hi) : "l"(v));
}
__device__ __forceinline__ float sig_(float x) {
    return __fdividef(1.0f, 1.0f + __expf(-x));
}
__device__ __forceinline__ float tanh_(float x) {
    float a = fabsf(x);
    float e = __expf(-2.0f * a);
    float r = __fdividef(1.0f - e, 1.0f + e);
    return copysignf(r, x);
}
__device__ __forceinline__ float cell_update(ull aIF, ull aGO, float& c) {
    float gi, gf, gg, go;
    unpack2(aIF, gi, gf);
    unpack2(aGO, gg, go);
    float cn = sig_(gf) * c + sig_(gi) * tanh_(gg);
    c = cn;
    return sig_(go) * tanh_(cn);
}

// Accumulators: [hsub][IF/GO][row], 16 x 64-bit.
struct Acc { ull a[2][2][4]; };

// nk iterations: per k, 32B weights (2h x 4 gates) + 16B values (4 rows).
__device__ __forceinline__ void gemm_block(const float*& w, const float* v, int nk, Acc& A) {
    #pragma unroll 4
    for (int k = 0; k < nk; ++k) {
        ulonglong2 wh0 = *reinterpret_cast<const ulonglong2*>(w);       // h0: (i,f),(g,o)
        ulonglong2 wh1 = *reinterpret_cast<const ulonglong2*>(w + 4);   // h1: (i,f),(g,o)
        float4 vv = *reinterpret_cast<const float4*>(v);
        w += 8; v += BROW;
        ull p0 = pack2(vv.x, vv.x);
        ull p1 = pack2(vv.y, vv.y);
        ull p2 = pack2(vv.z, vv.z);
        ull p3 = pack2(vv.w, vv.w);
        A.a[0][0][0] = ffma2(wh0.x, p0, A.a[0][0][0]);
        A.a[0][1][0] = ffma2(wh0.y, p0, A.a[0][1][0]);
        A.a[0][0][1] = ffma2(wh0.x, p1, A.a[0][0][1]);
        A.a[0][1][1] = ffma2(wh0.y, p1, A.a[0][1][1]);
        A.a[0][0][2] = ffma2(wh0.x, p2, A.a[0][0][2]);
        A.a[0][1][2] = ffma2(wh0.y, p2, A.a[0][1][2]);
        A.a[0][0][3] = ffma2(wh0.x, p3, A.a[0][0][3]);
        A.a[0][1][3] = ffma2(wh0.y, p3, A.a[0][1][3]);
        A.a[1][0][0] = ffma2(wh1.x, p0, A.a[1][0][0]);
        A.a[1][1][0] = ffma2(wh1.y, p0, A.a[1][1][0]);
        A.a[1][0][1] = ffma2(wh1.x, p1, A.a[1][0][1]);
        A.a[1][1][1] = ffma2(wh1.y, p1, A.a[1][1][1]);
        A.a[1][0][2] = ffma2(wh1.x, p2, A.a[1][0][2]);
        A.a[1][1][2] = ffma2(wh1.y, p2, A.a[1][1][2]);
        A.a[1][0][3] = ffma2(wh1.x, p3, A.a[1][0][3]);
        A.a[1][1][3] = ffma2(wh1.y, p3, A.a[1][1][3]);
    }
}

extern __shared__ __align__(16) char smem_raw[];

__global__ __launch_bounds__(NTHR, 1)
void lstm_seq_kernel(const float* __restrict__ xin,
                     const float* __restrict__ W_ih1, const float* __restrict__ W_hh1,
                     const float* __restrict__ b_ih1, const float* __restrict__ b_hh1,
                     const float* __restrict__ W_ih2, const float* __restrict__ W_hh2,
                     const float* __restrict__ b_ih2, const float* __restrict__ b_hh2,
                     const float* __restrict__ W_lin, const float* __restrict__ b_lin,
                     float* __restrict__ out)
{
    SmemLayout* s = reinterpret_cast<SmemLayout*>(smem_raw);
    const int tid = threadIdx.x;

    // ---------------- one-time smem staging ----------------
    for (int i = tid; i < HPAIR * 52 * 8; i += NTHR) {
        int hp = i / (52 * 8); int rem = i - hp * 52 * 8; int k = rem >> 3; int j = rem & 7;
        int h = 2 * hp + (j >> 2); int g = j & 3;
        float v = 0.f;
        if (h < Hh) {
            if (k < Hh)       v = W_hh1[(g * Hh + h) * Hh + k];
            else if (k == Hh) v = W_ih1[g * Hh + h];
        }
        s->WA[hp][k][j] = v;
    }
    for (int i = tid; i < HPAIR * 104 * 8; i += NTHR) {
        int hp = i / (104 * 8); int rem = i - hp * 104 * 8; int k = rem >> 3; int j = rem & 7;
        int h = 2 * hp + (j >> 2); int g = j & 3;
        float v = 0.f;
        if (h < Hh) {
            if (k < Hh)                      v = W_ih2[(g * Hh + h) * Hh + k];
            else if (k >= 52 && k < 52 + Hh) v = W_hh2[(g * Hh + h) * Hh + (k - 52)];
        }
        s->WB[hp][k][j] = v;
    }
    for (int i = tid; i < HPAIR * 8; i += NTHR) {
        int hp = i >> 3, j = i & 7;
        int h = 2 * hp + (j >> 2); int g = j & 3;
        float a = 0.f, b = 0.f;
        if (h < Hh) {
            a = b_ih1[g * Hh + h] + b_hh1[g * Hh + h];
            b = b_ih2[g * Hh + h] + b_hh2[g * Hh + h];
        }
        s->BA[hp][j] = a; s->BB[hp][j] = b;
    }
    for (int i = tid; i < 2 * 52 * BROW; i += NTHR) {
        s->B1[0][0][i] = 0.f;
        s->B2[0][0][i] = 0.f;
    }
    if (tid < 52) s->WL[tid] = (tid < Hh) ? W_lin[tid] : 0.f;
    if (tid == 0) s->blin = b_lin[0];
    __syncthreads();

    // ---------------- per-thread roles ----------------
    const bool active = tid < NACT;
    const int hp   = tid / RG4;        // 0..25
    const int rg   = tid - hp * RG4;   // 0..6
    const int voff = rg * 4;           // float offset into state rows (4 batch rows)

    // head: 224 threads = 28 rows x 8 lanes; lane 0 of each row also stages x
    const int  hrow      = tid >> 3;   // 0..27
    const int  hj        = tid & 7;    // 0..7
    const bool is_stager = (hj == 0);
    const int  grow      = blockIdx.x * RPC + hrow;

    float c1[2][4] = {}, c2[2][4] = {};
    float xv = 0.f, out_prev = 0.f;
    if (is_stager && grow < BATCH) xv = xin[grow * T_IN];   // prefetch x[t=0]

    const float* waBase = &s->WA[hp][0][0];
    const float* wbBase = &s->WB[hp][0][0];

    // ---------------- time loop ----------------
    for (int t = 0; t < T_TOT; ++t) {
        const int p = t & 1;
        float* cur1 = &s->B1[p][0][0];
        float* nxt1 = &s->B1[p ^ 1][0][0];
        float* cur2 = &s->B2[p][0][0];
        float* nxt2 = &s->B2[p ^ 1][0][0];

        // stage x_t into x slot (row 51 of cur1); prefetch x_{t+1}
        if (is_stager) {
            cur1[Hh * BROW + hrow] = (t < T_IN) ? xv : out_prev;
            if (t + 1 < T_IN && grow < BATCH) xv = xin[grow * T_IN + t + 1];
        }
        __syncthreads();   // S1: x staged; previous step fully complete

        Acc A;
        if (active) {
            // gates1 = [W_hh1 | W_ih1] @ [h1; x] + bias1
            #pragma unroll
            for (int hs = 0; hs < 2; ++hs) {
                ull bif = pack2(s->BA[hp][4 * hs + 0], s->BA[hp][4 * hs + 1]);
                ull bgo = pack2(s->BA[hp][4 * hs + 2], s->BA[hp][4 * hs + 3]);
                #pragma unroll
                for (int r = 0; r < 4; ++r) { A.a[hs][0][r] = bif; A.a[hs][1][r] = bgo; }
            }
            const float* w = waBase;
            gemm_block(w, cur1 + voff, 52, A);

            #pragma unroll
            for (int hs = 0; hs < 2; ++hs) {
                int h = 2 * hp + hs;
                if (h < Hh) {
                    float h0 = cell_update(A.a[hs][0][0], A.a[hs][1][0], c1[hs][0]);
                    float h1v = cell_update(A.a[hs][0][1], A.a[hs][1][1], c1[hs][1]);
                    float h2v = cell_update(A.a[hs][0][2], A.a[hs][1][2], c1[hs][2]);
                    float h3v = cell_update(A.a[hs][0][3], A.a[hs][1][3], c1[hs][3]);
                    *reinterpret_cast<float4*>(nxt1 + h * BROW + voff) =
                        make_float4(h0, h1v, h2v, h3v);
                }
            }
        }
        __syncthreads();   // S2: h1_new visible

        if (active) {
            // gates2 = [W_ih2 | W_hh2] @ [h1_new; h2] + bias2 (x slot hits zero weights)
            #pragma unroll
            for (int hs = 0; hs < 2; ++hs) {
                ull bif = pack2(s->BB[hp][4 * hs + 0], s->BB[hp][4 * hs + 1]);
                ull bgo = pack2(s->BB[hp][4 * hs + 2], s->BB[hp][4 * hs + 3]);
                #pragma unroll
                for (int r = 0; r < 4; ++r) { A.a[hs][0][r] = bif; A.a[hs][1][r] = bgo; }
            }
            const float* w = wbBase;
            gemm_block(w, nxt1 + voff, 52, A);
            gemm_block(w, cur2 + voff, 52, A);

            #pragma unroll
            for (int hs = 0; hs < 2; ++hs) {
                int h = 2 * hp + hs;
                if (h < Hh) {
                    float h0 = cell_update(A.a[hs][0][0], A.a[hs][1][0], c2[hs][0]);
                    float h1v = cell_update(A.a[hs][0][1], A.a[hs][1][1], c2[hs][1]);
                    float h2v = cell_update(A.a[hs][0][2], A.a[hs][1][2], c2[hs][2]);
                    float h3v = cell_update(A.a[hs][0][3], A.a[hs][1][3], c2[hs][3]);
                    *reinterpret_cast<float4*>(nxt2 + h * BROW + voff) =
                        make_float4(h0, h1v, h2v, h3v);
                }
            }
        }
        __syncthreads();   // S3: h2_new visible

        // linear head: out = W_lin . h2 + b_lin; 8 lanes/row, shuffle reduce
        {
            float a = 0.f;
            const float* col = nxt2 + hrow;
            #pragma unroll
            for (int k = hj; k < Hh; k += 8)
                a += s->WL[k] * col[k * BROW];
            a += __shfl_xor_sync(0xFFFFFFFFu, a, 1);
            a += __shfl_xor_sync(0xFFFFFFFFu, a, 2);
            a += __shfl_xor_sync(0xFFFFFFFFu, a, 4);
            if (is_stager) {
                float o = a + s->blin;
                out_prev = o;
                if (grow < BATCH) out[grow * T_TOT + t] = o;
            }
        }
    }
}

extern "C" void kernel_launch(void* const* d_in, const int* in_sizes, int n_in,
                              void* d_out, int out_size) {
    (void)in_sizes; (void)n_in; (void)out_size;
    const size_t smem = sizeof(SmemLayout);
    cudaFuncSetAttribute(lstm_seq_kernel, cudaFuncAttributeMaxDynamicSharedMemorySize, (int)smem);
    lstm_seq_kernel<<<NCTA, NTHR, smem>>>(
        (const float*)d_in[0],   // inputs [B, T]
        (const float*)d_in[1],   // W_ih1 [204,1]
        (const float*)d_in[2],   // W_hh1 [204,51]
        (const float*)d_in[3],   // b_ih1 [204]
        (const float*)d_in[4],   // b_hh1 [204]
        (const float*)d_in[5],   // W_ih2 [204,51]
        (const float*)d_in[6],   // W_hh2 [204,51]
        (const float*)d_in[7],   // b_ih2 [204]
        (const float*)d_in[8],   // b_hh2 [204]
        (const float*)d_in[9],   // W_lin [1,51]
        (const float*)d_in[10],  // b_lin [1]
        (float*)d_out);          // out [B, 1100]
}